// round 11
// baseline (speedup 1.0000x reference)
#include <cuda_runtime.h>
#include <cuda_fp16.h>
#include <cstdint>
#include <cmath>

#define HIDDEN 3072
#define NHEADS 24
#define NKV 8
#define HD 128
#define ROTD 96
#define OPSZ 5120
#define RLORA 256
#define BB 2
#define SS 2048
#define MTOT (BB*SS)
#define ATT_SCALE 0.08838834764831845f
#define LORA_SC 2.0f

typedef unsigned int u32;

// ---------------- static scratch heap ----------------
constexpr size_t SZ_X    = (size_t)MTOT*HIDDEN;
constexpr size_t SZ_WQKV = (size_t)OPSZ*HIDDEN;
constexpr size_t SZ_AQ   = (size_t)RLORA*HIDDEN;
constexpr size_t SZ_BQ   = (size_t)OPSZ*RLORA;
constexpr size_t SZ_WO   = (size_t)HIDDEN*HIDDEN;
constexpr size_t SZ_BO   = (size_t)HIDDEN*RLORA;
constexpr size_t SZ_QKV  = (size_t)MTOT*OPSZ;
constexpr size_t SZ_T    = (size_t)MTOT*RLORA;
constexpr size_t SZ_Q    = (size_t)BB*NHEADS*SS*HD;
constexpr size_t SZ_KV   = (size_t)BB*NKV*SS*HD;

constexpr size_t al256(size_t x){ return (x+255)&~(size_t)255; }

constexpr size_t O_XHI = 0;
constexpr size_t O_XLO = O_XHI + al256(SZ_X*2);
constexpr size_t O_WQH = O_XLO + al256(SZ_X*2);
constexpr size_t O_AQH = O_WQH + al256(SZ_WQKV*2);
constexpr size_t O_BQH = O_AQH + al256(SZ_AQ*2);
constexpr size_t O_WOH = O_BQH + al256(SZ_BQ*2);
constexpr size_t O_AOH = O_WOH + al256(SZ_WO*2);
constexpr size_t O_BOH = O_AOH + al256(SZ_AQ*2);
constexpr size_t O_T1H = O_BOH + al256(SZ_BO*2);
constexpr size_t O_T1L = O_T1H + al256(SZ_T*2);
constexpr size_t O_T2H = O_T1L + al256(SZ_T*2);
constexpr size_t O_T2L = O_T2H + al256(SZ_T*2);
constexpr size_t O_QH  = O_T2L + al256(SZ_T*2);
constexpr size_t O_QL  = O_QH  + al256(SZ_Q*2);
constexpr size_t O_KH  = O_QL  + al256(SZ_Q*2);
constexpr size_t O_VH  = O_KH  + al256(SZ_KV*2);
constexpr size_t O_ATH = O_VH  + al256(SZ_KV*2);
constexpr size_t O_ATL = O_ATH + al256(SZ_X*2);
constexpr size_t O_QKV = O_ATL + al256(SZ_X*2);
constexpr size_t HEAP_BYTES = O_QKV + al256(SZ_QKV*4);

__device__ __align__(256) unsigned char g_heap[HEAP_BYTES];

// ---------------- helpers ----------------
__device__ __forceinline__ void mma16816(float* c, const u32* a, const u32* b) {
    asm volatile("mma.sync.aligned.m16n8k16.row.col.f32.f16.f16.f32 "
        "{%0,%1,%2,%3}, {%4,%5,%6,%7}, {%8,%9}, {%0,%1,%2,%3};\n"
        : "+f"(c[0]), "+f"(c[1]), "+f"(c[2]), "+f"(c[3])
        : "r"(a[0]), "r"(a[1]), "r"(a[2]), "r"(a[3]), "r"(b[0]), "r"(b[1]));
}
__device__ __forceinline__ void cp_async16(void* smem, const void* g) {
    u32 sa = (u32)__cvta_generic_to_shared(smem);
    asm volatile("cp.async.cg.shared.global [%0], [%1], 16;\n" :: "r"(sa), "l"(g));
}
#define CP_COMMIT() asm volatile("cp.async.commit_group;\n")
#define CP_WAIT1()  asm volatile("cp.async.wait_group 1;\n")
#define CP_WAIT0()  asm volatile("cp.async.wait_group 0;\n")

__device__ __forceinline__ void ldsm4(u32& r0, u32& r1, u32& r2, u32& r3, const __half* p) {
    u32 a = (u32)__cvta_generic_to_shared(p);
    asm volatile("ldmatrix.sync.aligned.m8n8.x4.shared.b16 {%0,%1,%2,%3}, [%4];\n"
        : "=r"(r0), "=r"(r1), "=r"(r2), "=r"(r3) : "r"(a));
}
__device__ __forceinline__ void ldsm4t(u32& r0, u32& r1, u32& r2, u32& r3, const __half* p) {
    u32 a = (u32)__cvta_generic_to_shared(p);
    asm volatile("ldmatrix.sync.aligned.m8n8.x4.trans.shared.b16 {%0,%1,%2,%3}, [%4];\n"
        : "=r"(r0), "=r"(r1), "=r"(r2), "=r"(r3) : "r"(a));
}

__device__ __forceinline__ void split_pack(float x, float y, u32& hi, u32& lo) {
    __half hx = __float2half_rn(x);
    __half hy = __float2half_rn(y);
    __half lx = __float2half_rn(x - __half2float(hx));
    __half ly = __float2half_rn(y - __half2float(hy));
    hi = ((u32)__half_as_ushort(hy) << 16) | (u32)__half_as_ushort(hx);
    lo = ((u32)__half_as_ushort(ly) << 16) | (u32)__half_as_ushort(lx);
}
__device__ __forceinline__ u32 pack_h2(float x, float y) {
    __half hx = __float2half_rn(x);
    __half hy = __float2half_rn(y);
    return ((u32)__half_as_ushort(hy) << 16) | (u32)__half_as_ushort(hx);
}

// ---------------- merged prep kernels ----------------
constexpr size_t N4_X  = SZ_X/4;
constexpr size_t N4_WQ = SZ_WQKV/4;
constexpr size_t N4_AQ = SZ_AQ/4;
constexpr size_t N4_BQ = SZ_BQ/4;
constexpr size_t N4_MAIN = N4_X + N4_WQ + N4_AQ + N4_BQ;

__global__ void prep_main(const float* __restrict__ x, const float* __restrict__ Wq,
                          const float* __restrict__ Aq, const float* __restrict__ Bq,
                          __half* __restrict__ xh, __half* __restrict__ xl,
                          __half* __restrict__ wq, __half* __restrict__ aq,
                          __half* __restrict__ bq) {
    size_t i = (size_t)blockIdx.x * blockDim.x + threadIdx.x;
    if (i >= N4_MAIN) return;
    if (i < N4_X) {
        float4 v = ((const float4*)x)[i];
        u32 h0, l0, h1, l1;
        split_pack(v.x, v.y, h0, l0);
        split_pack(v.z, v.w, h1, l1);
        ((uint2*)xh)[i] = make_uint2(h0, h1);
        ((uint2*)xl)[i] = make_uint2(l0, l1);
        return;
    }
    const float* src; __half* dst; size_t j;
    if (i < N4_X + N4_WQ)       { j = i - N4_X;                src = Wq; dst = wq; }
    else if (i < N4_X + N4_WQ + N4_AQ) { j = i - N4_X - N4_WQ; src = Aq; dst = aq; }
    else                        { j = i - N4_X - N4_WQ - N4_AQ; src = Bq; dst = bq; }
    float4 v = ((const float4*)src)[j];
    ((uint2*)dst)[j] = make_uint2(pack_h2(v.x, v.y), pack_h2(v.z, v.w));
}

constexpr size_t N4_WO = SZ_WO/4;
constexpr size_t N4_AO = SZ_AQ/4;
constexpr size_t N4_BO = SZ_BO/4;
constexpr size_t N4_SEC = N4_WO + N4_AO + N4_BO;

__global__ void prep_sec(const float* __restrict__ Wo, const float* __restrict__ Ao,
                         const float* __restrict__ Bo,
                         __half* __restrict__ wo, __half* __restrict__ ao,
                         __half* __restrict__ bo) {
    size_t i = (size_t)blockIdx.x * blockDim.x + threadIdx.x;
    if (i >= N4_SEC) return;
    const float* src; __half* dst; size_t j;
    if (i < N4_WO)              { j = i;                src = Wo; dst = wo; }
    else if (i < N4_WO + N4_AO) { j = i - N4_WO;        src = Ao; dst = ao; }
    else                        { j = i - N4_WO - N4_AO; src = Bo; dst = bo; }
    float4 v = ((const float4*)src)[j];
    ((uint2*)dst)[j] = make_uint2(pack_h2(v.x, v.y), pack_h2(v.z, v.w));
}

// ---------------- templated GEMM, 3-stage cp.async pipeline ----------------
// C[M,N] = alpha * [A1|A2][M,K1+K2] @ ([B1|B2][N,K1+K2])^T
// A split hi/lo fp16 (2-pass), B fp16 single. Single __syncthreads per k-chunk.
#define GBK 32
#define GPK 40

template<int BM, int BN, int WN>
__global__ void __launch_bounds__(256, 2) gemm_split(
    const __half* __restrict__ A1h, const __half* __restrict__ A1l,
    const __half* __restrict__ A2h, const __half* __restrict__ A2l,
    const __half* __restrict__ B1h, const __half* __restrict__ B2h,
    float* __restrict__ C,
    __half* __restrict__ Oh, __half* __restrict__ Ol,
    int N, int K1, int K2, float alpha)
{
    constexpr int WNT = BN / WN;
    constexpr int NP  = WNT / 16;
    constexpr int AOFF = 0;
    constexpr int LOFF = BM * GPK;
    constexpr int BOFF = 2 * BM * GPK;
    constexpr int STAGE = (2 * BM + BN) * GPK;
    constexpr int A_T = BM * 4;          // 16B tasks per A array (32 halves/row = 4)
    constexpr int B_T = BN * 4;
    constexpr int TOT_T = 2 * A_T + B_T;

    extern __shared__ __half sm[];
    int tid = threadIdx.x;
    int bm = blockIdx.y * BM, bn = blockIdx.x * BN;
    int warp = tid >> 5, lane = tid & 31;
    int wm = warp / WN, wn = warp % WN;
    int g = lane >> 2, tg = lane & 3;

    auto load_stage = [&](int c) {
        __half* base = sm + (c % 3) * STAGE;
        int k0 = c * GBK;
        bool s2 = (k0 >= K1);
        int koff = s2 ? (k0 - K1) : k0;
        int sk = s2 ? K2 : K1;
        const __half* ah = (s2 ? A2h : A1h) + koff;
        const __half* al = (s2 ? A2l : A1l) + koff;
        const __half* bh = (s2 ? B2h : B1h) + koff;
        #pragma unroll
        for (int i = 0; i < TOT_T / 256; ++i) {
            int t = tid + i * 256;
            const __half* gsrc;
            int dst_off, row, ch;
            if (t < A_T) {
                row = t >> 2; ch = t & 3;
                gsrc = ah + (size_t)(bm + row) * sk + ch * 8;
                dst_off = AOFF;
            } else if (t < 2 * A_T) {
                int tt = t - A_T; row = tt >> 2; ch = tt & 3;
                gsrc = al + (size_t)(bm + row) * sk + ch * 8;
                dst_off = LOFF;
            } else {
                int tt = t - 2 * A_T; row = tt >> 2; ch = tt & 3;
                gsrc = bh + (size_t)(bn + row) * sk + ch * 8;
                dst_off = BOFF;
            }
            cp_async16(base + dst_off + row * GPK + ch * 8, gsrc);
        }
        CP_COMMIT();
    };

    float acc[2][2 * NP][4];
    #pragma unroll
    for (int a = 0; a < 2; ++a)
        #pragma unroll
        for (int b = 0; b < 2 * NP; ++b)
            #pragma unroll
            for (int c = 0; c < 4; ++c) acc[a][b][c] = 0.f;

    int a_row = lane & 15;
    int a_col = (lane >> 4) << 3;
    int b_row = (lane & 7) + ((lane >> 4) << 3);
    int b_col = ((lane >> 3) & 1) << 3;

    int nkt = (K1 + K2) / GBK;
    load_stage(0);
    if (nkt > 1) load_stage(1); else CP_COMMIT();

    for (int kt = 0; kt < nkt; ++kt) {
        CP_WAIT1();            // tile kt complete (pending <= 1)
        __syncthreads();       // all warps done reading stage (kt+2)%3 (= stage of kt-1)
        if (kt + 2 < nkt) load_stage(kt + 2); else CP_COMMIT();

        const __half* base = sm + (kt % 3) * STAGE;
        const __half* sAh = base + AOFF;
        const __half* sAl = base + LOFF;
        const __half* sB  = base + BOFF;
        #pragma unroll
        for (int ks = 0; ks < 2; ++ks) {
            int k0 = ks * 16;
            u32 ah[2][4], al[2][4];
            #pragma unroll
            for (int mt = 0; mt < 2; ++mt) {
                int r0 = wm * 32 + mt * 16 + a_row;
                ldsm4(ah[mt][0], ah[mt][1], ah[mt][2], ah[mt][3], sAh + r0 * GPK + k0 + a_col);
                ldsm4(al[mt][0], al[mt][1], al[mt][2], al[mt][3], sAl + r0 * GPK + k0 + a_col);
            }
            #pragma unroll
            for (int np = 0; np < NP; ++np) {
                int n0 = wn * WNT + np * 16 + b_row;
                u32 bh[4];
                ldsm4(bh[0], bh[1], bh[2], bh[3], sB + n0 * GPK + k0 + b_col);
                #pragma unroll
                for (int mt = 0; mt < 2; ++mt) {
                    mma16816(acc[mt][2*np],   ah[mt], bh);
                    mma16816(acc[mt][2*np],   al[mt], bh);
                    mma16816(acc[mt][2*np+1], ah[mt], bh + 2);
                    mma16816(acc[mt][2*np+1], al[mt], bh + 2);
                }
            }
        }
    }

    #pragma unroll
    for (int mt = 0; mt < 2; ++mt)
        #pragma unroll
        for (int j = 0; j < 2 * NP; ++j) {
            int np = j >> 1, half = j & 1;
            int row = bm + wm * 32 + mt * 16 + g;
            int col = bn + wn * WNT + np * 16 + half * 8 + 2 * tg;
            float v0 = alpha * acc[mt][j][0], v1 = alpha * acc[mt][j][1];
            float v2 = alpha * acc[mt][j][2], v3 = alpha * acc[mt][j][3];
            if (Oh) {
                u32 h0, l0, h1, l1;
                split_pack(v0, v1, h0, l0);
                split_pack(v2, v3, h1, l1);
                size_t i0 = ((size_t)row * N + col) >> 1;
                size_t i1 = ((size_t)(row + 8) * N + col) >> 1;
                ((u32*)Oh)[i0] = h0; ((u32*)Ol)[i0] = l0;
                ((u32*)Oh)[i1] = h1; ((u32*)Ol)[i1] = l1;
            } else {
                float* p0 = C + (size_t)row * N + col;
                float* p1 = C + (size_t)(row + 8) * N + col;
                p0[0] = v0; p0[1] = v1;
                p1[0] = v2; p1[1] = v3;
            }
        }
}

// ---------------- RoPE + split + scatter to [b,h,s,d] ----------------
__global__ void __launch_bounds__(256) rope_split(
    const float* __restrict__ qkv, const int* __restrict__ pos_ids,
    __half* __restrict__ Qh, __half* __restrict__ Ql,
    __half* __restrict__ Kh, __half* __restrict__ Vh)
{
    int bs = blockIdx.x;
    int b = bs / SS, s = bs % SS;
    __shared__ float cosv[ROTD], sinv[ROTD];
    int tid = threadIdx.x;
    if (tid < 48) {
        float invf = (float)pow(10000.0, -(double)tid / 48.0);
        float ang = (float)pos_ids[bs] * invf;
        float c = (float)cos((double)ang), sn = (float)sin((double)ang);
        cosv[tid] = c; cosv[tid + 48] = c;
        sinv[tid] = sn; sinv[tid + 48] = sn;
    }
    __syncthreads();
    const float* src = qkv + (size_t)bs * OPSZ;
    for (int e = tid; e < OPSZ; e += 256) {
        int d = e & 127;
        int hh = e >> 7;
        float v = src[e];
        bool isq = hh < NHEADS;
        bool isk = (hh >= NHEADS) && (hh < NHEADS + NKV);
        float outv = v;
        if ((isq || isk) && d < ROTD) {
            if (d < 48) outv = v * cosv[d] - src[e + 48] * sinv[d];
            else        outv = v * cosv[d] + src[e - 48] * sinv[d];
        }
        if (isq) {
            __half hi = __float2half_rn(outv);
            __half lo = __float2half_rn(outv - __half2float(hi));
            size_t dst = ((size_t)(b * NHEADS + hh) * SS + s) * HD + d;
            Qh[dst] = hi; Ql[dst] = lo;
        } else if (isk) {
            size_t dst = ((size_t)(b * NKV + (hh - NHEADS)) * SS + s) * HD + d;
            Kh[dst] = __float2half_rn(outv);
        } else {
            size_t dst = ((size_t)(b * NKV + (hh - NHEADS - NKV)) * SS + s) * HD + d;
            Vh[dst] = __float2half_rn(outv);
        }
    }
}

// ---------------- causal flash attention (GQA), fp16 2-pass, K/V double-buffered ----------------
#define FQP 136
#define FTILE (64 * FQP)

__global__ void __launch_bounds__(128) flash_attn(
    const __half* __restrict__ Qh, const __half* __restrict__ Ql,
    const __half* __restrict__ Kh, const __half* __restrict__ Vh,
    __half* __restrict__ AtH, __half* __restrict__ AtL)
{
    extern __shared__ __half fsm[];
    __half* sQh = fsm;
    __half* sQl = fsm + 1 * FTILE;
    // stages: K0 @2, V0 @3, K1 @4, V1 @5

    int qt = blockIdx.x, h = blockIdx.y, b = blockIdx.z;
    int kvh = h / (NHEADS / NKV);
    int tid = threadIdx.x, warp = tid >> 5, lane = tid & 31;
    int g = lane >> 2, tg = lane & 3;

    int a_row = warp * 16 + (lane & 15);
    int a_col = (lane >> 4) << 3;
    int b_row = (lane & 7) + ((lane >> 4) << 3);
    int b_col = ((lane >> 3) & 1) << 3;
    int v_row = (lane & 7) + (((lane >> 3) & 1) << 3);
    int v_col = ((lane >> 4) & 1) << 3;

    auto load_kv = [&](int kt) {
        int stage = kt & 1;
        __half* sK = fsm + (2 + 2 * stage) * FTILE;
        __half* sV = fsm + (3 + 2 * stage) * FTILE;
        size_t kbase = ((size_t)(b * NKV + kvh) * SS + (size_t)kt * 64) * HD;
        #pragma unroll
        for (int i = 0; i < 8; ++i) {
            int task = tid + i * 128;
            int row = task >> 4, ch = task & 15;
            cp_async16(sK + row * FQP + ch * 8, Kh + kbase + row * HD + ch * 8);
            cp_async16(sV + row * FQP + ch * 8, Vh + kbase + row * HD + ch * 8);
        }
        CP_COMMIT();
    };

    size_t qbase = ((size_t)(b * NHEADS + h) * SS + (size_t)qt * 64) * HD;
    #pragma unroll
    for (int i = 0; i < 8; ++i) {
        int task = tid + i * 128;
        int row = task >> 4, ch = task & 15;
        cp_async16(sQh + row * FQP + ch * 8, Qh + qbase + row * HD + ch * 8);
        cp_async16(sQl + row * FQP + ch * 8, Ql + qbase + row * HD + ch * 8);
    }
    CP_COMMIT();
    load_kv(0);

    float m0 = -1e30f, m1 = -1e30f, l0 = 0.f, l1 = 0.f;
    float oacc[16][4];
    #pragma unroll
    for (int i = 0; i < 16; ++i)
        #pragma unroll
        for (int r = 0; r < 4; ++r) oacc[i][r] = 0.f;

    for (int kt = 0; kt <= qt; ++kt) {
        CP_WAIT0();            // tile kt (and Q) complete
        __syncthreads();       // all warps done reading stage (kt+1)&1 from iter kt-1
        if (kt < qt) load_kv(kt + 1);   // issued post-sync: write target is dead

        const __half* sK = fsm + (2 + 2 * (kt & 1)) * FTILE;
        const __half* sV = fsm + (3 + 2 * (kt & 1)) * FTILE;

        float sacc[8][4];
        #pragma unroll
        for (int nt = 0; nt < 8; ++nt)
            #pragma unroll
            for (int r = 0; r < 4; ++r) sacc[nt][r] = 0.f;

        #pragma unroll
        for (int kc = 0; kc < 8; ++kc) {
            int k0 = kc * 16;
            u32 ah[4], al[4];
            ldsm4(ah[0], ah[1], ah[2], ah[3], sQh + a_row * FQP + k0 + a_col);
            ldsm4(al[0], al[1], al[2], al[3], sQl + a_row * FQP + k0 + a_col);
            #pragma unroll
            for (int np = 0; np < 4; ++np) {
                int n0 = np * 16 + b_row;
                u32 bh[4];
                ldsm4(bh[0], bh[1], bh[2], bh[3], sK + n0 * FQP + k0 + b_col);
                mma16816(sacc[2*np],   ah, bh);
                mma16816(sacc[2*np],   al, bh);
                mma16816(sacc[2*np+1], ah, bh + 2);
                mma16816(sacc[2*np+1], al, bh + 2);
            }
        }

        bool diag = (kt == qt);
        int row0 = qt * 64 + warp * 16 + g;
        #pragma unroll
        for (int nt = 0; nt < 8; ++nt)
            #pragma unroll
            for (int r = 0; r < 4; ++r) {
                float v = sacc[nt][r] * ATT_SCALE;
                if (diag) {
                    int col = kt * 64 + nt * 8 + 2 * tg + (r & 1);
                    int row = row0 + ((r >= 2) ? 8 : 0);
                    if (col > row) v = -1e30f;
                }
                sacc[nt][r] = v;
            }

        float rm0 = -1e30f, rm1 = -1e30f;
        #pragma unroll
        for (int nt = 0; nt < 8; ++nt) {
            rm0 = fmaxf(rm0, fmaxf(sacc[nt][0], sacc[nt][1]));
            rm1 = fmaxf(rm1, fmaxf(sacc[nt][2], sacc[nt][3]));
        }
        rm0 = fmaxf(rm0, __shfl_xor_sync(0xffffffffu, rm0, 1));
        rm0 = fmaxf(rm0, __shfl_xor_sync(0xffffffffu, rm0, 2));
        rm1 = fmaxf(rm1, __shfl_xor_sync(0xffffffffu, rm1, 1));
        rm1 = fmaxf(rm1, __shfl_xor_sync(0xffffffffu, rm1, 2));
        float nm0 = fmaxf(m0, rm0), nm1 = fmaxf(m1, rm1);
        float alpha0 = __expf(m0 - nm0), alpha1 = __expf(m1 - nm1);
        m0 = nm0; m1 = nm1;
        float rs0 = 0.f, rs1 = 0.f;
        #pragma unroll
        for (int nt = 0; nt < 8; ++nt) {
            sacc[nt][0] = __expf(sacc[nt][0] - m0); rs0 += sacc[nt][0];
            sacc[nt][1] = __expf(sacc[nt][1] - m0); rs0 += sacc[nt][1];
            sacc[nt][2] = __expf(sacc[nt][2] - m1); rs1 += sacc[nt][2];
            sacc[nt][3] = __expf(sacc[nt][3] - m1); rs1 += sacc[nt][3];
        }
        rs0 += __shfl_xor_sync(0xffffffffu, rs0, 1);
        rs0 += __shfl_xor_sync(0xffffffffu, rs0, 2);
        rs1 += __shfl_xor_sync(0xffffffffu, rs1, 1);
        rs1 += __shfl_xor_sync(0xffffffffu, rs1, 2);
        l0 = l0 * alpha0 + rs0;
        l1 = l1 * alpha1 + rs1;
        #pragma unroll
        for (int nt = 0; nt < 16; ++nt) {
            oacc[nt][0] *= alpha0; oacc[nt][1] *= alpha0;
            oacc[nt][2] *= alpha1; oacc[nt][3] *= alpha1;
        }

        #pragma unroll
        for (int kc2 = 0; kc2 < 4; ++kc2) {
            int kv0 = kc2 * 16;
            u32 ph4[4], pl4[4];
            split_pack(sacc[2*kc2][0],   sacc[2*kc2][1],   ph4[0], pl4[0]);
            split_pack(sacc[2*kc2][2],   sacc[2*kc2][3],   ph4[1], pl4[1]);
            split_pack(sacc[2*kc2+1][0], sacc[2*kc2+1][1], ph4[2], pl4[2]);
            split_pack(sacc[2*kc2+1][2], sacc[2*kc2+1][3], ph4[3], pl4[3]);
            #pragma unroll
            for (int np = 0; np < 8; ++np) {
                int d0 = np * 16 + v_col;
                u32 bh[4];
                ldsm4t(bh[0], bh[1], bh[2], bh[3], sV + (kv0 + v_row) * FQP + d0);
                mma16816(oacc[2*np],   ph4, bh);
                mma16816(oacc[2*np],   pl4, bh);
                mma16816(oacc[2*np+1], ph4, bh + 2);
                mma16816(oacc[2*np+1], pl4, bh + 2);
            }
        }
    }

    float inv0 = 1.f / l0, inv1 = 1.f / l1;
    int srow = qt * 64 + warp * 16 + g;
    #pragma unroll
    for (int nt = 0; nt < 16; ++nt) {
        int col = nt * 8 + 2 * tg;
        float a0 = oacc[nt][0] * inv0, a1 = oacc[nt][1] * inv0;
        float a2 = oacc[nt][2] * inv1, a3 = oacc[nt][3] * inv1;
        u32 h0, L0, h1, L1;
        split_pack(a0, a1, h0, L0);
        split_pack(a2, a3, h1, L1);
        size_t e0 = ((size_t)(b * SS + srow) * HIDDEN + h * HD + col) >> 1;
        size_t e1 = ((size_t)(b * SS + srow + 8) * HIDDEN + h * HD + col) >> 1;
        ((u32*)AtH)[e0] = h0; ((u32*)AtL)[e0] = L0;
        ((u32*)AtH)[e1] = h1; ((u32*)AtL)[e1] = L1;
    }
}

// ---------------- launch ----------------
extern "C" void kernel_launch(void* const* d_in, const int* in_sizes, int n_in,
                              void* d_out, int out_size) {
    const float* x    = (const float*)d_in[0];
    const float* Wqkv = (const float*)d_in[1];
    const float* Aqkv = (const float*)d_in[2];
    const float* Bqkv = (const float*)d_in[3];
    const float* Wo   = (const float*)d_in[4];
    const float* Ao   = (const float*)d_in[5];
    const float* Bo   = (const float*)d_in[6];
    const int*   pos  = (const int*)d_in[7];
    float* out = (float*)d_out;

    unsigned char* heap = nullptr;
    cudaGetSymbolAddress((void**)&heap, g_heap);

    size_t main_smem = (size_t)(2 * 128 + 128) * GPK * sizeof(__half) * 3;  // 3 stages
    size_t lora_smem = (size_t)(2 * 64 + 128) * GPK * sizeof(__half) * 3;
    size_t flash_smem = 6 * FTILE * sizeof(__half);   // Qh,Ql + 2 stages of K,V
    cudaFuncSetAttribute((const void*)gemm_split<128,128,2>, cudaFuncAttributeMaxDynamicSharedMemorySize, (int)main_smem);
    cudaFuncSetAttribute((const void*)gemm_split<64,128,4>,  cudaFuncAttributeMaxDynamicSharedMemorySize, (int)lora_smem);
    cudaFuncSetAttribute((const void*)flash_attn, cudaFuncAttributeMaxDynamicSharedMemorySize, (int)flash_smem);

#define HF(off) ((__half*)(heap + off))
#define FP(off) ((float*)(heap + off))

    // 1: prep x + first-half weights
    prep_main<<<(unsigned)((N4_MAIN + 255) / 256), 256>>>(
        x, Wqkv, Aqkv, Bqkv,
        HF(O_XHI), HF(O_XLO), HF(O_WQH), HF(O_AQH), HF(O_BQH));

    // 2: T1 = LORA_SC * x @ Aqkv^T  (hi/lo output)
    gemm_split<64,128,4><<<dim3(RLORA / 128, MTOT / 64), 256, lora_smem>>>(
        HF(O_XHI), HF(O_XLO), HF(O_XHI), HF(O_XLO),
        HF(O_AQH), HF(O_AQH),
        nullptr, HF(O_T1H), HF(O_T1L),
        RLORA, HIDDEN, 0, LORA_SC);

    // 3: prep second-half weights
    prep_sec<<<(unsigned)((N4_SEC + 255) / 256), 256>>>(
        Wo, Ao, Bo, HF(O_WOH), HF(O_AOH), HF(O_BOH));

    // 4: QKV = [x | T1] @ [Wqkv | Bqkv]^T   (fp32)   <-- ncu profiled slot
    gemm_split<128,128,2><<<dim3(OPSZ / 128, MTOT / 128), 256, main_smem>>>(
        HF(O_XHI), HF(O_XLO), HF(O_T1H), HF(O_T1L),
        HF(O_WQH), HF(O_BQH),
        FP(O_QKV), nullptr, nullptr,
        OPSZ, HIDDEN, RLORA, 1.0f);

    // 5: RoPE + scatter + split
    rope_split<<<MTOT, 256>>>(FP(O_QKV), pos,
        HF(O_QH), HF(O_QL), HF(O_KH), HF(O_VH));

    // 6: flash attention (writes hi/lo attn directly)
    flash_attn<<<dim3(SS / 64, NHEADS, BB), 128, flash_smem>>>(
        HF(O_QH), HF(O_QL), HF(O_KH), HF(O_VH),
        HF(O_ATH), HF(O_ATL));

    // 7: T2 = LORA_SC * attn @ Ao^T  (hi/lo output)
    gemm_split<64,128,4><<<dim3(RLORA / 128, MTOT / 64), 256, lora_smem>>>(
        HF(O_ATH), HF(O_ATL), HF(O_ATH), HF(O_ATL),
        HF(O_AOH), HF(O_AOH),
        nullptr, HF(O_T2H), HF(O_T2L),
        RLORA, HIDDEN, 0, LORA_SC);

    // 8: out = [attn | T2] @ [Wo | Bo]^T   (fp32)
    gemm_split<128,128,2><<<dim3(HIDDEN / 128, MTOT / 128), 256, main_smem>>>(
        HF(O_ATH), HF(O_ATL), HF(O_T2H), HF(O_T2L),
        HF(O_WOH), HF(O_BOH),
        out, nullptr, nullptr,
        HIDDEN, HIDDEN, RLORA, 1.0f);

#undef HF
#undef FP
}

// round 13
// speedup vs baseline: 1.1001x; 1.1001x over previous
#include <cuda_runtime.h>
#include <cuda_fp16.h>
#include <cstdint>
#include <cmath>

#define HIDDEN 3072
#define NHEADS 24
#define NKV 8
#define HD 128
#define ROTD 96
#define OPSZ 5120
#define RLORA 256
#define BB 2
#define SS 2048
#define MTOT (BB*SS)
#define ATT_SCALE 0.08838834764831845f
#define LORA_SC 2.0f

typedef unsigned int u32;

// ---------------- static scratch heap ----------------
constexpr size_t SZ_X    = (size_t)MTOT*HIDDEN;
constexpr size_t SZ_WQKV = (size_t)OPSZ*HIDDEN;
constexpr size_t SZ_AQ   = (size_t)RLORA*HIDDEN;
constexpr size_t SZ_BQ   = (size_t)OPSZ*RLORA;
constexpr size_t SZ_WO   = (size_t)HIDDEN*HIDDEN;
constexpr size_t SZ_BO   = (size_t)HIDDEN*RLORA;
constexpr size_t SZ_QKV  = (size_t)MTOT*OPSZ;
constexpr size_t SZ_T    = (size_t)MTOT*RLORA;
constexpr size_t SZ_Q    = (size_t)BB*NHEADS*SS*HD;
constexpr size_t SZ_KV   = (size_t)BB*NKV*SS*HD;

constexpr size_t al256(size_t x){ return (x+255)&~(size_t)255; }

constexpr size_t O_XHI = 0;
constexpr size_t O_XLO = O_XHI + al256(SZ_X*2);
constexpr size_t O_WQH = O_XLO + al256(SZ_X*2);
constexpr size_t O_AQH = O_WQH + al256(SZ_WQKV*2);
constexpr size_t O_BQH = O_AQH + al256(SZ_AQ*2);
constexpr size_t O_WOH = O_BQH + al256(SZ_BQ*2);
constexpr size_t O_AOH = O_WOH + al256(SZ_WO*2);
constexpr size_t O_BOH = O_AOH + al256(SZ_AQ*2);
constexpr size_t O_T1H = O_BOH + al256(SZ_BO*2);
constexpr size_t O_T1L = O_T1H + al256(SZ_T*2);
constexpr size_t O_T2H = O_T1L + al256(SZ_T*2);
constexpr size_t O_T2L = O_T2H + al256(SZ_T*2);
constexpr size_t O_QH  = O_T2L + al256(SZ_T*2);
constexpr size_t O_QL  = O_QH  + al256(SZ_Q*2);
constexpr size_t O_KH  = O_QL  + al256(SZ_Q*2);
constexpr size_t O_VH  = O_KH  + al256(SZ_KV*2);
constexpr size_t O_ATH = O_VH  + al256(SZ_KV*2);
constexpr size_t O_ATL = O_ATH + al256(SZ_X*2);
constexpr size_t O_QKV = O_ATL + al256(SZ_X*2);
constexpr size_t HEAP_BYTES = O_QKV + al256(SZ_QKV*4);

__device__ __align__(256) unsigned char g_heap[HEAP_BYTES];

// ---------------- helpers ----------------
__device__ __forceinline__ void mma16816(float* c, const u32* a, const u32* b) {
    asm volatile("mma.sync.aligned.m16n8k16.row.col.f32.f16.f16.f32 "
        "{%0,%1,%2,%3}, {%4,%5,%6,%7}, {%8,%9}, {%0,%1,%2,%3};\n"
        : "+f"(c[0]), "+f"(c[1]), "+f"(c[2]), "+f"(c[3])
        : "r"(a[0]), "r"(a[1]), "r"(a[2]), "r"(a[3]), "r"(b[0]), "r"(b[1]));
}
__device__ __forceinline__ void cp_async16(void* smem, const void* g) {
    u32 sa = (u32)__cvta_generic_to_shared(smem);
    asm volatile("cp.async.cg.shared.global [%0], [%1], 16;\n" :: "r"(sa), "l"(g));
}
#define CP_COMMIT() asm volatile("cp.async.commit_group;\n")
#define CP_WAIT1()  asm volatile("cp.async.wait_group 1;\n")
#define CP_WAIT0()  asm volatile("cp.async.wait_group 0;\n")

__device__ __forceinline__ void ldsm4(u32& r0, u32& r1, u32& r2, u32& r3, const __half* p) {
    u32 a = (u32)__cvta_generic_to_shared(p);
    asm volatile("ldmatrix.sync.aligned.m8n8.x4.shared.b16 {%0,%1,%2,%3}, [%4];\n"
        : "=r"(r0), "=r"(r1), "=r"(r2), "=r"(r3) : "r"(a));
}
__device__ __forceinline__ void ldsm4t(u32& r0, u32& r1, u32& r2, u32& r3, const __half* p) {
    u32 a = (u32)__cvta_generic_to_shared(p);
    asm volatile("ldmatrix.sync.aligned.m8n8.x4.trans.shared.b16 {%0,%1,%2,%3}, [%4];\n"
        : "=r"(r0), "=r"(r1), "=r"(r2), "=r"(r3) : "r"(a));
}

__device__ __forceinline__ void split_pack(float x, float y, u32& hi, u32& lo) {
    __half hx = __float2half_rn(x);
    __half hy = __float2half_rn(y);
    __half lx = __float2half_rn(x - __half2float(hx));
    __half ly = __float2half_rn(y - __half2float(hy));
    hi = ((u32)__half_as_ushort(hy) << 16) | (u32)__half_as_ushort(hx);
    lo = ((u32)__half_as_ushort(ly) << 16) | (u32)__half_as_ushort(lx);
}
__device__ __forceinline__ u32 pack_h2(float x, float y) {
    __half hx = __float2half_rn(x);
    __half hy = __float2half_rn(y);
    return ((u32)__half_as_ushort(hy) << 16) | (u32)__half_as_ushort(hx);
}

// ---------------- merged prep kernels ----------------
constexpr size_t N4_X  = SZ_X/4;
constexpr size_t N4_WQ = SZ_WQKV/4;
constexpr size_t N4_AQ = SZ_AQ/4;
constexpr size_t N4_BQ = SZ_BQ/4;
constexpr size_t N4_MAIN = N4_X + N4_WQ + N4_AQ + N4_BQ;

__global__ void prep_main(const float* __restrict__ x, const float* __restrict__ Wq,
                          const float* __restrict__ Aq, const float* __restrict__ Bq,
                          __half* __restrict__ xh, __half* __restrict__ xl,
                          __half* __restrict__ wq, __half* __restrict__ aq,
                          __half* __restrict__ bq) {
    size_t i = (size_t)blockIdx.x * blockDim.x + threadIdx.x;
    if (i >= N4_MAIN) return;
    if (i < N4_X) {
        float4 v = ((const float4*)x)[i];
        u32 h0, l0, h1, l1;
        split_pack(v.x, v.y, h0, l0);
        split_pack(v.z, v.w, h1, l1);
        ((uint2*)xh)[i] = make_uint2(h0, h1);
        ((uint2*)xl)[i] = make_uint2(l0, l1);
        return;
    }
    const float* src; __half* dst; size_t j;
    if (i < N4_X + N4_WQ)       { j = i - N4_X;                src = Wq; dst = wq; }
    else if (i < N4_X + N4_WQ + N4_AQ) { j = i - N4_X - N4_WQ; src = Aq; dst = aq; }
    else                        { j = i - N4_X - N4_WQ - N4_AQ; src = Bq; dst = bq; }
    float4 v = ((const float4*)src)[j];
    ((uint2*)dst)[j] = make_uint2(pack_h2(v.x, v.y), pack_h2(v.z, v.w));
}

constexpr size_t N4_WO = SZ_WO/4;
constexpr size_t N4_AO = SZ_AQ/4;
constexpr size_t N4_BO = SZ_BO/4;
constexpr size_t N4_SEC = N4_WO + N4_AO + N4_BO;

__global__ void prep_sec(const float* __restrict__ Wo, const float* __restrict__ Ao,
                         const float* __restrict__ Bo,
                         __half* __restrict__ wo, __half* __restrict__ ao,
                         __half* __restrict__ bo) {
    size_t i = (size_t)blockIdx.x * blockDim.x + threadIdx.x;
    if (i >= N4_SEC) return;
    const float* src; __half* dst; size_t j;
    if (i < N4_WO)              { j = i;                src = Wo; dst = wo; }
    else if (i < N4_WO + N4_AO) { j = i - N4_WO;        src = Ao; dst = ao; }
    else                        { j = i - N4_WO - N4_AO; src = Bo; dst = bo; }
    float4 v = ((const float4*)src)[j];
    ((uint2*)dst)[j] = make_uint2(pack_h2(v.x, v.y), pack_h2(v.z, v.w));
}

// ---------------- templated GEMM, 2-stage (R9 structure), reordered MMA ----------------
// C[M,N] = alpha * [A1|A2][M,K1+K2] @ ([B1|B2][N,K1+K2])^T
// A split hi/lo fp16 (2-pass), B fp16 single.
#define GBK 64
#define GPK 72

template<int BM, int BN, int WN>
__global__ void __launch_bounds__(256, 2) gemm_split(
    const __half* __restrict__ A1h, const __half* __restrict__ A1l,
    const __half* __restrict__ A2h, const __half* __restrict__ A2l,
    const __half* __restrict__ B1h, const __half* __restrict__ B2h,
    float* __restrict__ C,
    __half* __restrict__ Oh, __half* __restrict__ Ol,
    int N, int K1, int K2, float alpha)
{
    constexpr int WNT = BN / WN;
    constexpr int NP  = WNT / 16;
    constexpr int AOFF = 0;
    constexpr int LOFF = BM * GPK;
    constexpr int BOFF = 2 * BM * GPK;
    constexpr int STAGE = (2 * BM + BN) * GPK;
    constexpr int A_T = BM * 8;          // 16B tasks per A array (64 halves/row = 8)
    constexpr int B_T = BN * 8;
    constexpr int TOT_T = 2 * A_T + B_T;

    extern __shared__ __half sm[];
    int tid = threadIdx.x;
    int bm = blockIdx.y * BM, bn = blockIdx.x * BN;
    int warp = tid >> 5, lane = tid & 31;
    int wm = warp / WN, wn = warp % WN;
    int g = lane >> 2, tg = lane & 3;

    auto load_stage = [&](int c) {
        __half* base = sm + (c & 1) * STAGE;
        int k0 = c * GBK;
        bool s2 = (k0 >= K1);
        int koff = s2 ? (k0 - K1) : k0;
        int sk = s2 ? K2 : K1;
        const __half* ah = (s2 ? A2h : A1h) + koff;
        const __half* al = (s2 ? A2l : A1l) + koff;
        const __half* bh = (s2 ? B2h : B1h) + koff;
        #pragma unroll
        for (int i = 0; i < TOT_T / 256; ++i) {
            int t = tid + i * 256;
            const __half* gsrc;
            int dst_off, row, ch;
            if (t < A_T) {
                row = t >> 3; ch = t & 7;
                gsrc = ah + (size_t)(bm + row) * sk + ch * 8;
                dst_off = AOFF;
            } else if (t < 2 * A_T) {
                int tt = t - A_T; row = tt >> 3; ch = tt & 7;
                gsrc = al + (size_t)(bm + row) * sk + ch * 8;
                dst_off = LOFF;
            } else {
                int tt = t - 2 * A_T; row = tt >> 3; ch = tt & 7;
                gsrc = bh + (size_t)(bn + row) * sk + ch * 8;
                dst_off = BOFF;
            }
            cp_async16(base + dst_off + row * GPK + ch * 8, gsrc);
        }
        CP_COMMIT();
    };

    float acc[2][2 * NP][4];
    #pragma unroll
    for (int a = 0; a < 2; ++a)
        #pragma unroll
        for (int b = 0; b < 2 * NP; ++b)
            #pragma unroll
            for (int c = 0; c < 4; ++c) acc[a][b][c] = 0.f;

    int a_row = lane & 15;
    int a_col = (lane >> 4) << 3;
    int b_row = (lane & 7) + ((lane >> 4) << 3);
    int b_col = ((lane >> 3) & 1) << 3;

    int nkt = (K1 + K2) / GBK;
    load_stage(0);
    for (int kt = 0; kt < nkt; ++kt) {
        if (kt + 1 < nkt) load_stage(kt + 1); else CP_COMMIT();
        CP_WAIT1();
        __syncthreads();
        const __half* base = sm + (kt & 1) * STAGE;
        const __half* sAh = base + AOFF;
        const __half* sAl = base + LOFF;
        const __half* sB  = base + BOFF;
        #pragma unroll
        for (int ks = 0; ks < 4; ++ks) {
            int k0 = ks * 16;
            u32 ah[2][4], al[2][4], bh[NP][4];
            #pragma unroll
            for (int mt = 0; mt < 2; ++mt) {
                int r0 = wm * 32 + mt * 16 + a_row;
                ldsm4(ah[mt][0], ah[mt][1], ah[mt][2], ah[mt][3], sAh + r0 * GPK + k0 + a_col);
                ldsm4(al[mt][0], al[mt][1], al[mt][2], al[mt][3], sAl + r0 * GPK + k0 + a_col);
            }
            #pragma unroll
            for (int np = 0; np < NP; ++np) {
                int n0 = wn * WNT + np * 16 + b_row;
                ldsm4(bh[np][0], bh[np][1], bh[np][2], bh[np][3], sB + n0 * GPK + k0 + b_col);
            }
            // hi pass over all accumulators (RAW distance = 2*NP*2)
            #pragma unroll
            for (int np = 0; np < NP; ++np)
                #pragma unroll
                for (int mt = 0; mt < 2; ++mt) {
                    mma16816(acc[mt][2*np],   ah[mt], bh[np]);
                    mma16816(acc[mt][2*np+1], ah[mt], bh[np] + 2);
                }
            // lo pass
            #pragma unroll
            for (int np = 0; np < NP; ++np)
                #pragma unroll
                for (int mt = 0; mt < 2; ++mt) {
                    mma16816(acc[mt][2*np],   al[mt], bh[np]);
                    mma16816(acc[mt][2*np+1], al[mt], bh[np] + 2);
                }
        }
        __syncthreads();
    }

    #pragma unroll
    for (int mt = 0; mt < 2; ++mt)
        #pragma unroll
        for (int j = 0; j < 2 * NP; ++j) {
            int np = j >> 1, half = j & 1;
            int row = bm + wm * 32 + mt * 16 + g;
            int col = bn + wn * WNT + np * 16 + half * 8 + 2 * tg;
            float v0 = alpha * acc[mt][j][0], v1 = alpha * acc[mt][j][1];
            float v2 = alpha * acc[mt][j][2], v3 = alpha * acc[mt][j][3];
            if (Oh) {
                u32 h0, l0, h1, l1;
                split_pack(v0, v1, h0, l0);
                split_pack(v2, v3, h1, l1);
                size_t i0 = ((size_t)row * N + col) >> 1;
                size_t i1 = ((size_t)(row + 8) * N + col) >> 1;
                ((u32*)Oh)[i0] = h0; ((u32*)Ol)[i0] = l0;
                ((u32*)Oh)[i1] = h1; ((u32*)Ol)[i1] = l1;
            } else {
                float* p0 = C + (size_t)row * N + col;
                float* p1 = C + (size_t)(row + 8) * N + col;
                p0[0] = v0; p0[1] = v1;
                p1[0] = v2; p1[1] = v3;
            }
        }
}

// ---------------- RoPE + split + scatter to [b,h,s,d] ----------------
__global__ void __launch_bounds__(256) rope_split(
    const float* __restrict__ qkv, const int* __restrict__ pos_ids,
    __half* __restrict__ Qh, __half* __restrict__ Ql,
    __half* __restrict__ Kh, __half* __restrict__ Vh)
{
    int bs = blockIdx.x;
    int b = bs / SS, s = bs % SS;
    __shared__ float cosv[ROTD], sinv[ROTD];
    int tid = threadIdx.x;
    if (tid < 48) {
        float invf = (float)pow(10000.0, -(double)tid / 48.0);
        float ang = (float)pos_ids[bs] * invf;
        float c = (float)cos((double)ang), sn = (float)sin((double)ang);
        cosv[tid] = c; cosv[tid + 48] = c;
        sinv[tid] = sn; sinv[tid + 48] = sn;
    }
    __syncthreads();
    const float* src = qkv + (size_t)bs * OPSZ;
    for (int e = tid; e < OPSZ; e += 256) {
        int d = e & 127;
        int hh = e >> 7;
        float v = src[e];
        bool isq = hh < NHEADS;
        bool isk = (hh >= NHEADS) && (hh < NHEADS + NKV);
        float outv = v;
        if ((isq || isk) && d < ROTD) {
            if (d < 48) outv = v * cosv[d] - src[e + 48] * sinv[d];
            else        outv = v * cosv[d] + src[e - 48] * sinv[d];
        }
        if (isq) {
            __half hi = __float2half_rn(outv);
            __half lo = __float2half_rn(outv - __half2float(hi));
            size_t dst = ((size_t)(b * NHEADS + hh) * SS + s) * HD + d;
            Qh[dst] = hi; Ql[dst] = lo;
        } else if (isk) {
            size_t dst = ((size_t)(b * NKV + (hh - NHEADS)) * SS + s) * HD + d;
            Kh[dst] = __float2half_rn(outv);
        } else {
            size_t dst = ((size_t)(b * NKV + (hh - NHEADS - NKV)) * SS + s) * HD + d;
            Vh[dst] = __float2half_rn(outv);
        }
    }
}

// ---------------- causal flash attention (GQA), fp16 2-pass, reordered MMA ----------------
#define FQP 136

__global__ void __launch_bounds__(128) flash_attn(
    const __half* __restrict__ Qh, const __half* __restrict__ Ql,
    const __half* __restrict__ Kh, const __half* __restrict__ Vh,
    __half* __restrict__ AtH, __half* __restrict__ AtL)
{
    extern __shared__ __half fsm[];
    __half* sQh = fsm;
    __half* sQl = fsm + 1 * 64 * FQP;
    __half* sKh = fsm + 2 * 64 * FQP;
    __half* sVh = fsm + 3 * 64 * FQP;

    int qt = blockIdx.x, h = blockIdx.y, b = blockIdx.z;
    int kvh = h / (NHEADS / NKV);
    int tid = threadIdx.x, warp = tid >> 5, lane = tid & 31;
    int g = lane >> 2, tg = lane & 3;

    int a_row = warp * 16 + (lane & 15);
    int a_col = (lane >> 4) << 3;
    int b_row = (lane & 7) + ((lane >> 4) << 3);
    int b_col = ((lane >> 3) & 1) << 3;
    int v_row = (lane & 7) + (((lane >> 3) & 1) << 3);
    int v_col = ((lane >> 4) & 1) << 3;

    size_t qbase = ((size_t)(b * NHEADS + h) * SS + (size_t)qt * 64) * HD;
    #pragma unroll
    for (int i = 0; i < 8; ++i) {
        int task = tid + i * 128;
        int row = task >> 4, ch = task & 15;
        cp_async16(sQh + row * FQP + ch * 8, Qh + qbase + row * HD + ch * 8);
        cp_async16(sQl + row * FQP + ch * 8, Ql + qbase + row * HD + ch * 8);
    }
    CP_COMMIT();

    float m0 = -1e30f, m1 = -1e30f, l0 = 0.f, l1 = 0.f;
    float oacc[16][4];
    #pragma unroll
    for (int i = 0; i < 16; ++i)
        #pragma unroll
        for (int r = 0; r < 4; ++r) oacc[i][r] = 0.f;

    for (int kt = 0; kt <= qt; ++kt) {
        size_t kbase = ((size_t)(b * NKV + kvh) * SS + (size_t)kt * 64) * HD;
        #pragma unroll
        for (int i = 0; i < 8; ++i) {
            int task = tid + i * 128;
            int row = task >> 4, ch = task & 15;
            cp_async16(sKh + row * FQP + ch * 8, Kh + kbase + row * HD + ch * 8);
            cp_async16(sVh + row * FQP + ch * 8, Vh + kbase + row * HD + ch * 8);
        }
        CP_COMMIT();
        CP_WAIT0();
        __syncthreads();

        float sacc[8][4];
        #pragma unroll
        for (int nt = 0; nt < 8; ++nt)
            #pragma unroll
            for (int r = 0; r < 4; ++r) sacc[nt][r] = 0.f;

        #pragma unroll
        for (int kc = 0; kc < 8; ++kc) {
            int k0 = kc * 16;
            u32 ah[4], al[4], bh[4][4];
            ldsm4(ah[0], ah[1], ah[2], ah[3], sQh + a_row * FQP + k0 + a_col);
            ldsm4(al[0], al[1], al[2], al[3], sQl + a_row * FQP + k0 + a_col);
            #pragma unroll
            for (int np = 0; np < 4; ++np) {
                int n0 = np * 16 + b_row;
                ldsm4(bh[np][0], bh[np][1], bh[np][2], bh[np][3], sKh + n0 * FQP + k0 + b_col);
            }
            // hi pass
            #pragma unroll
            for (int np = 0; np < 4; ++np) {
                mma16816(sacc[2*np],   ah, bh[np]);
                mma16816(sacc[2*np+1], ah, bh[np] + 2);
            }
            // lo pass
            #pragma unroll
            for (int np = 0; np < 4; ++np) {
                mma16816(sacc[2*np],   al, bh[np]);
                mma16816(sacc[2*np+1], al, bh[np] + 2);
            }
        }

        bool diag = (kt == qt);
        int row0 = qt * 64 + warp * 16 + g;
        #pragma unroll
        for (int nt = 0; nt < 8; ++nt)
            #pragma unroll
            for (int r = 0; r < 4; ++r) {
                float v = sacc[nt][r] * ATT_SCALE;
                if (diag) {
                    int col = kt * 64 + nt * 8 + 2 * tg + (r & 1);
                    int row = row0 + ((r >= 2) ? 8 : 0);
                    if (col > row) v = -1e30f;
                }
                sacc[nt][r] = v;
            }

        float rm0 = -1e30f, rm1 = -1e30f;
        #pragma unroll
        for (int nt = 0; nt < 8; ++nt) {
            rm0 = fmaxf(rm0, fmaxf(sacc[nt][0], sacc[nt][1]));
            rm1 = fmaxf(rm1, fmaxf(sacc[nt][2], sacc[nt][3]));
        }
        rm0 = fmaxf(rm0, __shfl_xor_sync(0xffffffffu, rm0, 1));
        rm0 = fmaxf(rm0, __shfl_xor_sync(0xffffffffu, rm0, 2));
        rm1 = fmaxf(rm1, __shfl_xor_sync(0xffffffffu, rm1, 1));
        rm1 = fmaxf(rm1, __shfl_xor_sync(0xffffffffu, rm1, 2));
        float nm0 = fmaxf(m0, rm0), nm1 = fmaxf(m1, rm1);
        float alpha0 = __expf(m0 - nm0), alpha1 = __expf(m1 - nm1);
        m0 = nm0; m1 = nm1;
        float rs0 = 0.f, rs1 = 0.f;
        #pragma unroll
        for (int nt = 0; nt < 8; ++nt) {
            sacc[nt][0] = __expf(sacc[nt][0] - m0); rs0 += sacc[nt][0];
            sacc[nt][1] = __expf(sacc[nt][1] - m0); rs0 += sacc[nt][1];
            sacc[nt][2] = __expf(sacc[nt][2] - m1); rs1 += sacc[nt][2];
            sacc[nt][3] = __expf(sacc[nt][3] - m1); rs1 += sacc[nt][3];
        }
        rs0 += __shfl_xor_sync(0xffffffffu, rs0, 1);
        rs0 += __shfl_xor_sync(0xffffffffu, rs0, 2);
        rs1 += __shfl_xor_sync(0xffffffffu, rs1, 1);
        rs1 += __shfl_xor_sync(0xffffffffu, rs1, 2);
        l0 = l0 * alpha0 + rs0;
        l1 = l1 * alpha1 + rs1;
        #pragma unroll
        for (int nt = 0; nt < 16; ++nt) {
            oacc[nt][0] *= alpha0; oacc[nt][1] *= alpha0;
            oacc[nt][2] *= alpha1; oacc[nt][3] *= alpha1;
        }

        #pragma unroll
        for (int kc2 = 0; kc2 < 4; ++kc2) {
            int kv0 = kc2 * 16;
            u32 ph4[4], pl4[4];
            split_pack(sacc[2*kc2][0],   sacc[2*kc2][1],   ph4[0], pl4[0]);
            split_pack(sacc[2*kc2][2],   sacc[2*kc2][3],   ph4[1], pl4[1]);
            split_pack(sacc[2*kc2+1][0], sacc[2*kc2+1][1], ph4[2], pl4[2]);
            split_pack(sacc[2*kc2+1][2], sacc[2*kc2+1][3], ph4[3], pl4[3]);
            #pragma unroll
            for (int np = 0; np < 8; ++np) {
                int d0 = np * 16 + v_col;
                u32 bh[4];
                ldsm4t(bh[0], bh[1], bh[2], bh[3], sVh + (kv0 + v_row) * FQP + d0);
                mma16816(oacc[2*np],   ph4, bh);
                mma16816(oacc[2*np+1], ph4, bh + 2);
                mma16816(oacc[2*np],   pl4, bh);
                mma16816(oacc[2*np+1], pl4, bh + 2);
            }
        }
        __syncthreads();
    }

    float inv0 = 1.f / l0, inv1 = 1.f / l1;
    int srow = qt * 64 + warp * 16 + g;
    #pragma unroll
    for (int nt = 0; nt < 16; ++nt) {
        int col = nt * 8 + 2 * tg;
        float a0 = oacc[nt][0] * inv0, a1 = oacc[nt][1] * inv0;
        float a2 = oacc[nt][2] * inv1, a3 = oacc[nt][3] * inv1;
        u32 h0, L0, h1, L1;
        split_pack(a0, a1, h0, L0);
        split_pack(a2, a3, h1, L1);
        size_t e0 = ((size_t)(b * SS + srow) * HIDDEN + h * HD + col) >> 1;
        size_t e1 = ((size_t)(b * SS + srow + 8) * HIDDEN + h * HD + col) >> 1;
        ((u32*)AtH)[e0] = h0; ((u32*)AtL)[e0] = L0;
        ((u32*)AtH)[e1] = h1; ((u32*)AtL)[e1] = L1;
    }
}

// ---------------- launch ----------------
extern "C" void kernel_launch(void* const* d_in, const int* in_sizes, int n_in,
                              void* d_out, int out_size) {
    const float* x    = (const float*)d_in[0];
    const float* Wqkv = (const float*)d_in[1];
    const float* Aqkv = (const float*)d_in[2];
    const float* Bqkv = (const float*)d_in[3];
    const float* Wo   = (const float*)d_in[4];
    const float* Ao   = (const float*)d_in[5];
    const float* Bo   = (const float*)d_in[6];
    const int*   pos  = (const int*)d_in[7];
    float* out = (float*)d_out;

    unsigned char* heap = nullptr;
    cudaGetSymbolAddress((void**)&heap, g_heap);

    size_t main_smem = (size_t)(2 * 128 + 128) * GPK * sizeof(__half) * 2;  // 2 stages
    size_t lora_smem = (size_t)(2 * 64 + 128) * GPK * sizeof(__half) * 2;
    size_t flash_smem = 4 * 64 * FQP * sizeof(__half);
    cudaFuncSetAttribute((const void*)gemm_split<128,128,2>, cudaFuncAttributeMaxDynamicSharedMemorySize, (int)main_smem);
    cudaFuncSetAttribute((const void*)gemm_split<64,128,4>,  cudaFuncAttributeMaxDynamicSharedMemorySize, (int)lora_smem);
    cudaFuncSetAttribute((const void*)flash_attn, cudaFuncAttributeMaxDynamicSharedMemorySize, (int)flash_smem);

#define HF(off) ((__half*)(heap + off))
#define FP(off) ((float*)(heap + off))

    // 1: prep x + first-half weights
    prep_main<<<(unsigned)((N4_MAIN + 255) / 256), 256>>>(
        x, Wqkv, Aqkv, Bqkv,
        HF(O_XHI), HF(O_XLO), HF(O_WQH), HF(O_AQH), HF(O_BQH));

    // 2: T1 = LORA_SC * x @ Aqkv^T  (hi/lo output)
    gemm_split<64,128,4><<<dim3(RLORA / 128, MTOT / 64), 256, lora_smem>>>(
        HF(O_XHI), HF(O_XLO), HF(O_XHI), HF(O_XLO),
        HF(O_AQH), HF(O_AQH),
        nullptr, HF(O_T1H), HF(O_T1L),
        RLORA, HIDDEN, 0, LORA_SC);

    // 3: prep second-half weights
    prep_sec<<<(unsigned)((N4_SEC + 255) / 256), 256>>>(
        Wo, Ao, Bo, HF(O_WOH), HF(O_AOH), HF(O_BOH));

    // 4: QKV = [x | T1] @ [Wqkv | Bqkv]^T   (fp32)   <-- ncu profiled slot
    gemm_split<128,128,2><<<dim3(OPSZ / 128, MTOT / 128), 256, main_smem>>>(
        HF(O_XHI), HF(O_XLO), HF(O_T1H), HF(O_T1L),
        HF(O_WQH), HF(O_BQH),
        FP(O_QKV), nullptr, nullptr,
        OPSZ, HIDDEN, RLORA, 1.0f);

    // 5: RoPE + scatter + split
    rope_split<<<MTOT, 256>>>(FP(O_QKV), pos,
        HF(O_QH), HF(O_QL), HF(O_KH), HF(O_VH));

    // 6: flash attention (writes hi/lo attn directly)
    flash_attn<<<dim3(SS / 64, NHEADS, BB), 128, flash_smem>>>(
        HF(O_QH), HF(O_QL), HF(O_KH), HF(O_VH),
        HF(O_ATH), HF(O_ATL));

    // 7: T2 = LORA_SC * attn @ Ao^T  (hi/lo output)
    gemm_split<64,128,4><<<dim3(RLORA / 128, MTOT / 64), 256, lora_smem>>>(
        HF(O_ATH), HF(O_ATL), HF(O_ATH), HF(O_ATL),
        HF(O_AOH), HF(O_AOH),
        nullptr, HF(O_T2H), HF(O_T2L),
        RLORA, HIDDEN, 0, LORA_SC);

    // 8: out = [attn | T2] @ [Wo | Bo]^T   (fp32)
    gemm_split<128,128,2><<<dim3(HIDDEN / 128, MTOT / 128), 256, main_smem>>>(
        HF(O_ATH), HF(O_ATL), HF(O_T2H), HF(O_T2L),
        HF(O_WOH), HF(O_BOH),
        out, nullptr, nullptr,
        HIDDEN, HIDDEN, RLORA, 1.0f);

#undef HF
#undef FP
}

// round 14
// speedup vs baseline: 1.1511x; 1.0464x over previous
#include <cuda_runtime.h>
#include <cuda_fp16.h>
#include <cstdint>
#include <cmath>

#define HIDDEN 3072
#define NHEADS 24
#define NKV 8
#define HD 128
#define ROTD 96
#define OPSZ 5120
#define RLORA 256
#define BB 2
#define SS 2048
#define MTOT (BB*SS)
#define ATT_SCALE 0.08838834764831845f
#define LORA_SC 2.0f

typedef unsigned int u32;

// ---------------- static scratch heap ----------------
constexpr size_t SZ_X    = (size_t)MTOT*HIDDEN;
constexpr size_t SZ_WQKV = (size_t)OPSZ*HIDDEN;
constexpr size_t SZ_AQ   = (size_t)RLORA*HIDDEN;
constexpr size_t SZ_BQ   = (size_t)OPSZ*RLORA;
constexpr size_t SZ_WO   = (size_t)HIDDEN*HIDDEN;
constexpr size_t SZ_BO   = (size_t)HIDDEN*RLORA;
constexpr size_t SZ_QKV  = (size_t)MTOT*OPSZ;
constexpr size_t SZ_T    = (size_t)MTOT*RLORA;
constexpr size_t SZ_Q    = (size_t)BB*NHEADS*SS*HD;
constexpr size_t SZ_KV   = (size_t)BB*NKV*SS*HD;

constexpr size_t al256(size_t x){ return (x+255)&~(size_t)255; }

constexpr size_t O_XHI = 0;
constexpr size_t O_XLO = O_XHI + al256(SZ_X*2);
constexpr size_t O_WQH = O_XLO + al256(SZ_X*2);
constexpr size_t O_AQH = O_WQH + al256(SZ_WQKV*2);
constexpr size_t O_BQH = O_AQH + al256(SZ_AQ*2);
constexpr size_t O_WOH = O_BQH + al256(SZ_BQ*2);
constexpr size_t O_AOH = O_WOH + al256(SZ_WO*2);
constexpr size_t O_BOH = O_AOH + al256(SZ_AQ*2);
constexpr size_t O_T1H = O_BOH + al256(SZ_BO*2);
constexpr size_t O_T1L = O_T1H + al256(SZ_T*2);
constexpr size_t O_T2H = O_T1L + al256(SZ_T*2);
constexpr size_t O_T2L = O_T2H + al256(SZ_T*2);
constexpr size_t O_QH  = O_T2L + al256(SZ_T*2);
constexpr size_t O_QL  = O_QH  + al256(SZ_Q*2);
constexpr size_t O_KH  = O_QL  + al256(SZ_Q*2);
constexpr size_t O_VH  = O_KH  + al256(SZ_KV*2);
constexpr size_t O_ATH = O_VH  + al256(SZ_KV*2);
constexpr size_t O_ATL = O_ATH + al256(SZ_X*2);
constexpr size_t O_QKV = O_ATL + al256(SZ_X*2);
constexpr size_t HEAP_BYTES = O_QKV + al256(SZ_QKV*4);

__device__ __align__(256) unsigned char g_heap[HEAP_BYTES];

// ---------------- helpers ----------------
__device__ __forceinline__ void mma16816(float* c, const u32* a, const u32* b) {
    asm volatile("mma.sync.aligned.m16n8k16.row.col.f32.f16.f16.f32 "
        "{%0,%1,%2,%3}, {%4,%5,%6,%7}, {%8,%9}, {%0,%1,%2,%3};\n"
        : "+f"(c[0]), "+f"(c[1]), "+f"(c[2]), "+f"(c[3])
        : "r"(a[0]), "r"(a[1]), "r"(a[2]), "r"(a[3]), "r"(b[0]), "r"(b[1]));
}
__device__ __forceinline__ void cp_async16(void* smem, const void* g) {
    u32 sa = (u32)__cvta_generic_to_shared(smem);
    asm volatile("cp.async.cg.shared.global [%0], [%1], 16;\n" :: "r"(sa), "l"(g));
}
#define CP_COMMIT() asm volatile("cp.async.commit_group;\n")
#define CP_WAIT1()  asm volatile("cp.async.wait_group 1;\n")
#define CP_WAIT0()  asm volatile("cp.async.wait_group 0;\n")

__device__ __forceinline__ void ldsm4(u32& r0, u32& r1, u32& r2, u32& r3, const __half* p) {
    u32 a = (u32)__cvta_generic_to_shared(p);
    asm volatile("ldmatrix.sync.aligned.m8n8.x4.shared.b16 {%0,%1,%2,%3}, [%4];\n"
        : "=r"(r0), "=r"(r1), "=r"(r2), "=r"(r3) : "r"(a));
}
__device__ __forceinline__ void ldsm4t(u32& r0, u32& r1, u32& r2, u32& r3, const __half* p) {
    u32 a = (u32)__cvta_generic_to_shared(p);
    asm volatile("ldmatrix.sync.aligned.m8n8.x4.trans.shared.b16 {%0,%1,%2,%3}, [%4];\n"
        : "=r"(r0), "=r"(r1), "=r"(r2), "=r"(r3) : "r"(a));
}

__device__ __forceinline__ void split_pack(float x, float y, u32& hi, u32& lo) {
    __half hx = __float2half_rn(x);
    __half hy = __float2half_rn(y);
    __half lx = __float2half_rn(x - __half2float(hx));
    __half ly = __float2half_rn(y - __half2float(hy));
    hi = ((u32)__half_as_ushort(hy) << 16) | (u32)__half_as_ushort(hx);
    lo = ((u32)__half_as_ushort(ly) << 16) | (u32)__half_as_ushort(lx);
}
__device__ __forceinline__ u32 pack_h2(float x, float y) {
    __half hx = __float2half_rn(x);
    __half hy = __float2half_rn(y);
    return ((u32)__half_as_ushort(hy) << 16) | (u32)__half_as_ushort(hx);
}

// ---------------- merged prep kernels ----------------
constexpr size_t N4_X  = SZ_X/4;
constexpr size_t N4_WQ = SZ_WQKV/4;
constexpr size_t N4_AQ = SZ_AQ/4;
constexpr size_t N4_BQ = SZ_BQ/4;
constexpr size_t N4_MAIN = N4_X + N4_WQ + N4_AQ + N4_BQ;

__global__ void prep_main(const float* __restrict__ x, const float* __restrict__ Wq,
                          const float* __restrict__ Aq, const float* __restrict__ Bq,
                          __half* __restrict__ xh, __half* __restrict__ xl,
                          __half* __restrict__ wq, __half* __restrict__ aq,
                          __half* __restrict__ bq) {
    size_t i = (size_t)blockIdx.x * blockDim.x + threadIdx.x;
    if (i >= N4_MAIN) return;
    if (i < N4_X) {
        float4 v = ((const float4*)x)[i];
        u32 h0, l0, h1, l1;
        split_pack(v.x, v.y, h0, l0);
        split_pack(v.z, v.w, h1, l1);
        ((uint2*)xh)[i] = make_uint2(h0, h1);
        ((uint2*)xl)[i] = make_uint2(l0, l1);
        return;
    }
    const float* src; __half* dst; size_t j;
    if (i < N4_X + N4_WQ)       { j = i - N4_X;                src = Wq; dst = wq; }
    else if (i < N4_X + N4_WQ + N4_AQ) { j = i - N4_X - N4_WQ; src = Aq; dst = aq; }
    else                        { j = i - N4_X - N4_WQ - N4_AQ; src = Bq; dst = bq; }
    float4 v = ((const float4*)src)[j];
    ((uint2*)dst)[j] = make_uint2(pack_h2(v.x, v.y), pack_h2(v.z, v.w));
}

constexpr size_t N4_WO = SZ_WO/4;
constexpr size_t N4_AO = SZ_AQ/4;
constexpr size_t N4_BO = SZ_BO/4;
constexpr size_t N4_SEC = N4_WO + N4_AO + N4_BO;

__global__ void prep_sec(const float* __restrict__ Wo, const float* __restrict__ Ao,
                         const float* __restrict__ Bo,
                         __half* __restrict__ wo, __half* __restrict__ ao,
                         __half* __restrict__ bo) {
    size_t i = (size_t)blockIdx.x * blockDim.x + threadIdx.x;
    if (i >= N4_SEC) return;
    const float* src; __half* dst; size_t j;
    if (i < N4_WO)              { j = i;                src = Wo; dst = wo; }
    else if (i < N4_WO + N4_AO) { j = i - N4_WO;        src = Ao; dst = ao; }
    else                        { j = i - N4_WO - N4_AO; src = Bo; dst = bo; }
    float4 v = ((const float4*)src)[j];
    ((uint2*)dst)[j] = make_uint2(pack_h2(v.x, v.y), pack_h2(v.z, v.w));
}

// ---------------- templated GEMM, 2-stage, 64x128 tile, 3 CTAs/SM ----------------
// C[M,N] = alpha * [A1|A2][M,K1+K2] @ ([B1|B2][N,K1+K2])^T
// A split hi/lo fp16 (2-pass), B fp16 single.
#define GBK 64
#define GPK 72

template<int BM, int BN, int WN>
__global__ void __launch_bounds__(256, 3) gemm_split(
    const __half* __restrict__ A1h, const __half* __restrict__ A1l,
    const __half* __restrict__ A2h, const __half* __restrict__ A2l,
    const __half* __restrict__ B1h, const __half* __restrict__ B2h,
    float* __restrict__ C,
    __half* __restrict__ Oh, __half* __restrict__ Ol,
    int N, int K1, int K2, float alpha)
{
    constexpr int WNT = BN / WN;
    constexpr int NP  = WNT / 16;
    constexpr int AOFF = 0;
    constexpr int LOFF = BM * GPK;
    constexpr int BOFF = 2 * BM * GPK;
    constexpr int STAGE = (2 * BM + BN) * GPK;
    constexpr int A_T = BM * 8;          // 16B tasks per A array (64 halves/row = 8)
    constexpr int B_T = BN * 8;
    constexpr int TOT_T = 2 * A_T + B_T;

    extern __shared__ __half sm[];
    int tid = threadIdx.x;
    int bm = blockIdx.y * BM, bn = blockIdx.x * BN;
    int warp = tid >> 5, lane = tid & 31;
    int wm = warp / WN, wn = warp % WN;
    int g = lane >> 2, tg = lane & 3;

    auto load_stage = [&](int c) {
        __half* base = sm + (c & 1) * STAGE;
        int k0 = c * GBK;
        bool s2 = (k0 >= K1);
        int koff = s2 ? (k0 - K1) : k0;
        int sk = s2 ? K2 : K1;
        const __half* ah = (s2 ? A2h : A1h) + koff;
        const __half* al = (s2 ? A2l : A1l) + koff;
        const __half* bh = (s2 ? B2h : B1h) + koff;
        #pragma unroll
        for (int i = 0; i < TOT_T / 256; ++i) {
            int t = tid + i * 256;
            const __half* gsrc;
            int dst_off, row, ch;
            if (t < A_T) {
                row = t >> 3; ch = t & 7;
                gsrc = ah + (size_t)(bm + row) * sk + ch * 8;
                dst_off = AOFF;
            } else if (t < 2 * A_T) {
                int tt = t - A_T; row = tt >> 3; ch = tt & 7;
                gsrc = al + (size_t)(bm + row) * sk + ch * 8;
                dst_off = LOFF;
            } else {
                int tt = t - 2 * A_T; row = tt >> 3; ch = tt & 7;
                gsrc = bh + (size_t)(bn + row) * sk + ch * 8;
                dst_off = BOFF;
            }
            cp_async16(base + dst_off + row * GPK + ch * 8, gsrc);
        }
        CP_COMMIT();
    };

    float acc[2][2 * NP][4];
    #pragma unroll
    for (int a = 0; a < 2; ++a)
        #pragma unroll
        for (int b = 0; b < 2 * NP; ++b)
            #pragma unroll
            for (int c = 0; c < 4; ++c) acc[a][b][c] = 0.f;

    int a_row = lane & 15;
    int a_col = (lane >> 4) << 3;
    int b_row = (lane & 7) + ((lane >> 4) << 3);
    int b_col = ((lane >> 3) & 1) << 3;

    int nkt = (K1 + K2) / GBK;
    load_stage(0);
    for (int kt = 0; kt < nkt; ++kt) {
        if (kt + 1 < nkt) load_stage(kt + 1); else CP_COMMIT();
        CP_WAIT1();
        __syncthreads();
        const __half* base = sm + (kt & 1) * STAGE;
        const __half* sAh = base + AOFF;
        const __half* sAl = base + LOFF;
        const __half* sB  = base + BOFF;
        #pragma unroll
        for (int ks = 0; ks < 4; ++ks) {
            int k0 = ks * 16;
            u32 ah[2][4], al[2][4], bh[NP][4];
            #pragma unroll
            for (int mt = 0; mt < 2; ++mt) {
                int r0 = wm * 32 + mt * 16 + a_row;
                ldsm4(ah[mt][0], ah[mt][1], ah[mt][2], ah[mt][3], sAh + r0 * GPK + k0 + a_col);
                ldsm4(al[mt][0], al[mt][1], al[mt][2], al[mt][3], sAl + r0 * GPK + k0 + a_col);
            }
            #pragma unroll
            for (int np = 0; np < NP; ++np) {
                int n0 = wn * WNT + np * 16 + b_row;
                ldsm4(bh[np][0], bh[np][1], bh[np][2], bh[np][3], sB + n0 * GPK + k0 + b_col);
            }
            // hi pass over all accumulators
            #pragma unroll
            for (int np = 0; np < NP; ++np)
                #pragma unroll
                for (int mt = 0; mt < 2; ++mt) {
                    mma16816(acc[mt][2*np],   ah[mt], bh[np]);
                    mma16816(acc[mt][2*np+1], ah[mt], bh[np] + 2);
                }
            // lo pass
            #pragma unroll
            for (int np = 0; np < NP; ++np)
                #pragma unroll
                for (int mt = 0; mt < 2; ++mt) {
                    mma16816(acc[mt][2*np],   al[mt], bh[np]);
                    mma16816(acc[mt][2*np+1], al[mt], bh[np] + 2);
                }
        }
        __syncthreads();
    }

    #pragma unroll
    for (int mt = 0; mt < 2; ++mt)
        #pragma unroll
        for (int j = 0; j < 2 * NP; ++j) {
            int np = j >> 1, half = j & 1;
            int row = bm + wm * 32 + mt * 16 + g;
            int col = bn + wn * WNT + np * 16 + half * 8 + 2 * tg;
            float v0 = alpha * acc[mt][j][0], v1 = alpha * acc[mt][j][1];
            float v2 = alpha * acc[mt][j][2], v3 = alpha * acc[mt][j][3];
            if (Oh) {
                u32 h0, l0, h1, l1;
                split_pack(v0, v1, h0, l0);
                split_pack(v2, v3, h1, l1);
                size_t i0 = ((size_t)row * N + col) >> 1;
                size_t i1 = ((size_t)(row + 8) * N + col) >> 1;
                ((u32*)Oh)[i0] = h0; ((u32*)Ol)[i0] = l0;
                ((u32*)Oh)[i1] = h1; ((u32*)Ol)[i1] = l1;
            } else {
                float* p0 = C + (size_t)row * N + col;
                float* p1 = C + (size_t)(row + 8) * N + col;
                p0[0] = v0; p0[1] = v1;
                p1[0] = v2; p1[1] = v3;
            }
        }
}

// ---------------- RoPE + split + scatter to [b,h,s,d] ----------------
__global__ void __launch_bounds__(256) rope_split(
    const float* __restrict__ qkv, const int* __restrict__ pos_ids,
    __half* __restrict__ Qh, __half* __restrict__ Ql,
    __half* __restrict__ Kh, __half* __restrict__ Vh)
{
    int bs = blockIdx.x;
    int b = bs / SS, s = bs % SS;
    __shared__ float cosv[ROTD], sinv[ROTD];
    int tid = threadIdx.x;
    if (tid < 48) {
        float invf = (float)pow(10000.0, -(double)tid / 48.0);
        float ang = (float)pos_ids[bs] * invf;
        float c = (float)cos((double)ang), sn = (float)sin((double)ang);
        cosv[tid] = c; cosv[tid + 48] = c;
        sinv[tid] = sn; sinv[tid + 48] = sn;
    }
    __syncthreads();
    const float* src = qkv + (size_t)bs * OPSZ;
    for (int e = tid; e < OPSZ; e += 256) {
        int d = e & 127;
        int hh = e >> 7;
        float v = src[e];
        bool isq = hh < NHEADS;
        bool isk = (hh >= NHEADS) && (hh < NHEADS + NKV);
        float outv = v;
        if ((isq || isk) && d < ROTD) {
            if (d < 48) outv = v * cosv[d] - src[e + 48] * sinv[d];
            else        outv = v * cosv[d] + src[e - 48] * sinv[d];
        }
        if (isq) {
            __half hi = __float2half_rn(outv);
            __half lo = __float2half_rn(outv - __half2float(hi));
            size_t dst = ((size_t)(b * NHEADS + hh) * SS + s) * HD + d;
            Qh[dst] = hi; Ql[dst] = lo;
        } else if (isk) {
            size_t dst = ((size_t)(b * NKV + (hh - NHEADS)) * SS + s) * HD + d;
            Kh[dst] = __float2half_rn(outv);
        } else {
            size_t dst = ((size_t)(b * NKV + (hh - NHEADS - NKV)) * SS + s) * HD + d;
            Vh[dst] = __float2half_rn(outv);
        }
    }
}

// ---------------- causal flash attention (GQA), fp16 2-pass, reordered MMA ----------------
#define FQP 136

__global__ void __launch_bounds__(128) flash_attn(
    const __half* __restrict__ Qh, const __half* __restrict__ Ql,
    const __half* __restrict__ Kh, const __half* __restrict__ Vh,
    __half* __restrict__ AtH, __half* __restrict__ AtL)
{
    extern __shared__ __half fsm[];
    __half* sQh = fsm;
    __half* sQl = fsm + 1 * 64 * FQP;
    __half* sKh = fsm + 2 * 64 * FQP;
    __half* sVh = fsm + 3 * 64 * FQP;

    int qt = blockIdx.x, h = blockIdx.y, b = blockIdx.z;
    int kvh = h / (NHEADS / NKV);
    int tid = threadIdx.x, warp = tid >> 5, lane = tid & 31;
    int g = lane >> 2, tg = lane & 3;

    int a_row = warp * 16 + (lane & 15);
    int a_col = (lane >> 4) << 3;
    int b_row = (lane & 7) + ((lane >> 4) << 3);
    int b_col = ((lane >> 3) & 1) << 3;
    int v_row = (lane & 7) + (((lane >> 3) & 1) << 3);
    int v_col = ((lane >> 4) & 1) << 3;

    size_t qbase = ((size_t)(b * NHEADS + h) * SS + (size_t)qt * 64) * HD;
    #pragma unroll
    for (int i = 0; i < 8; ++i) {
        int task = tid + i * 128;
        int row = task >> 4, ch = task & 15;
        cp_async16(sQh + row * FQP + ch * 8, Qh + qbase + row * HD + ch * 8);
        cp_async16(sQl + row * FQP + ch * 8, Ql + qbase + row * HD + ch * 8);
    }
    CP_COMMIT();

    float m0 = -1e30f, m1 = -1e30f, l0 = 0.f, l1 = 0.f;
    float oacc[16][4];
    #pragma unroll
    for (int i = 0; i < 16; ++i)
        #pragma unroll
        for (int r = 0; r < 4; ++r) oacc[i][r] = 0.f;

    for (int kt = 0; kt <= qt; ++kt) {
        size_t kbase = ((size_t)(b * NKV + kvh) * SS + (size_t)kt * 64) * HD;
        #pragma unroll
        for (int i = 0; i < 8; ++i) {
            int task = tid + i * 128;
            int row = task >> 4, ch = task & 15;
            cp_async16(sKh + row * FQP + ch * 8, Kh + kbase + row * HD + ch * 8);
            cp_async16(sVh + row * FQP + ch * 8, Vh + kbase + row * HD + ch * 8);
        }
        CP_COMMIT();
        CP_WAIT0();
        __syncthreads();

        float sacc[8][4];
        #pragma unroll
        for (int nt = 0; nt < 8; ++nt)
            #pragma unroll
            for (int r = 0; r < 4; ++r) sacc[nt][r] = 0.f;

        #pragma unroll
        for (int kc = 0; kc < 8; ++kc) {
            int k0 = kc * 16;
            u32 ah[4], al[4], bh[4][4];
            ldsm4(ah[0], ah[1], ah[2], ah[3], sQh + a_row * FQP + k0 + a_col);
            ldsm4(al[0], al[1], al[2], al[3], sQl + a_row * FQP + k0 + a_col);
            #pragma unroll
            for (int np = 0; np < 4; ++np) {
                int n0 = np * 16 + b_row;
                ldsm4(bh[np][0], bh[np][1], bh[np][2], bh[np][3], sKh + n0 * FQP + k0 + b_col);
            }
            #pragma unroll
            for (int np = 0; np < 4; ++np) {
                mma16816(sacc[2*np],   ah, bh[np]);
                mma16816(sacc[2*np+1], ah, bh[np] + 2);
            }
            #pragma unroll
            for (int np = 0; np < 4; ++np) {
                mma16816(sacc[2*np],   al, bh[np]);
                mma16816(sacc[2*np+1], al, bh[np] + 2);
            }
        }

        bool diag = (kt == qt);
        int row0 = qt * 64 + warp * 16 + g;
        #pragma unroll
        for (int nt = 0; nt < 8; ++nt)
            #pragma unroll
            for (int r = 0; r < 4; ++r) {
                float v = sacc[nt][r] * ATT_SCALE;
                if (diag) {
                    int col = kt * 64 + nt * 8 + 2 * tg + (r & 1);
                    int row = row0 + ((r >= 2) ? 8 : 0);
                    if (col > row) v = -1e30f;
                }
                sacc[nt][r] = v;
            }

        float rm0 = -1e30f, rm1 = -1e30f;
        #pragma unroll
        for (int nt = 0; nt < 8; ++nt) {
            rm0 = fmaxf(rm0, fmaxf(sacc[nt][0], sacc[nt][1]));
            rm1 = fmaxf(rm1, fmaxf(sacc[nt][2], sacc[nt][3]));
        }
        rm0 = fmaxf(rm0, __shfl_xor_sync(0xffffffffu, rm0, 1));
        rm0 = fmaxf(rm0, __shfl_xor_sync(0xffffffffu, rm0, 2));
        rm1 = fmaxf(rm1, __shfl_xor_sync(0xffffffffu, rm1, 1));
        rm1 = fmaxf(rm1, __shfl_xor_sync(0xffffffffu, rm1, 2));
        float nm0 = fmaxf(m0, rm0), nm1 = fmaxf(m1, rm1);
        float alpha0 = __expf(m0 - nm0), alpha1 = __expf(m1 - nm1);
        m0 = nm0; m1 = nm1;
        float rs0 = 0.f, rs1 = 0.f;
        #pragma unroll
        for (int nt = 0; nt < 8; ++nt) {
            sacc[nt][0] = __expf(sacc[nt][0] - m0); rs0 += sacc[nt][0];
            sacc[nt][1] = __expf(sacc[nt][1] - m0); rs0 += sacc[nt][1];
            sacc[nt][2] = __expf(sacc[nt][2] - m1); rs1 += sacc[nt][2];
            sacc[nt][3] = __expf(sacc[nt][3] - m1); rs1 += sacc[nt][3];
        }
        rs0 += __shfl_xor_sync(0xffffffffu, rs0, 1);
        rs0 += __shfl_xor_sync(0xffffffffu, rs0, 2);
        rs1 += __shfl_xor_sync(0xffffffffu, rs1, 1);
        rs1 += __shfl_xor_sync(0xffffffffu, rs1, 2);
        l0 = l0 * alpha0 + rs0;
        l1 = l1 * alpha1 + rs1;
        #pragma unroll
        for (int nt = 0; nt < 16; ++nt) {
            oacc[nt][0] *= alpha0; oacc[nt][1] *= alpha0;
            oacc[nt][2] *= alpha1; oacc[nt][3] *= alpha1;
        }

        #pragma unroll
        for (int kc2 = 0; kc2 < 4; ++kc2) {
            int kv0 = kc2 * 16;
            u32 ph4[4], pl4[4];
            split_pack(sacc[2*kc2][0],   sacc[2*kc2][1],   ph4[0], pl4[0]);
            split_pack(sacc[2*kc2][2],   sacc[2*kc2][3],   ph4[1], pl4[1]);
            split_pack(sacc[2*kc2+1][0], sacc[2*kc2+1][1], ph4[2], pl4[2]);
            split_pack(sacc[2*kc2+1][2], sacc[2*kc2+1][3], ph4[3], pl4[3]);
            #pragma unroll
            for (int np = 0; np < 8; ++np) {
                int d0 = np * 16 + v_col;
                u32 bh[4];
                ldsm4t(bh[0], bh[1], bh[2], bh[3], sVh + (kv0 + v_row) * FQP + d0);
                mma16816(oacc[2*np],   ph4, bh);
                mma16816(oacc[2*np+1], ph4, bh + 2);
                mma16816(oacc[2*np],   pl4, bh);
                mma16816(oacc[2*np+1], pl4, bh + 2);
            }
        }
        __syncthreads();
    }

    float inv0 = 1.f / l0, inv1 = 1.f / l1;
    int srow = qt * 64 + warp * 16 + g;
    #pragma unroll
    for (int nt = 0; nt < 16; ++nt) {
        int col = nt * 8 + 2 * tg;
        float a0 = oacc[nt][0] * inv0, a1 = oacc[nt][1] * inv0;
        float a2 = oacc[nt][2] * inv1, a3 = oacc[nt][3] * inv1;
        u32 h0, L0, h1, L1;
        split_pack(a0, a1, h0, L0);
        split_pack(a2, a3, h1, L1);
        size_t e0 = ((size_t)(b * SS + srow) * HIDDEN + h * HD + col) >> 1;
        size_t e1 = ((size_t)(b * SS + srow + 8) * HIDDEN + h * HD + col) >> 1;
        ((u32*)AtH)[e0] = h0; ((u32*)AtL)[e0] = L0;
        ((u32*)AtH)[e1] = h1; ((u32*)AtL)[e1] = L1;
    }
}

// ---------------- launch ----------------
extern "C" void kernel_launch(void* const* d_in, const int* in_sizes, int n_in,
                              void* d_out, int out_size) {
    const float* x    = (const float*)d_in[0];
    const float* Wqkv = (const float*)d_in[1];
    const float* Aqkv = (const float*)d_in[2];
    const float* Bqkv = (const float*)d_in[3];
    const float* Wo   = (const float*)d_in[4];
    const float* Ao   = (const float*)d_in[5];
    const float* Bo   = (const float*)d_in[6];
    const int*   pos  = (const int*)d_in[7];
    float* out = (float*)d_out;

    unsigned char* heap = nullptr;
    cudaGetSymbolAddress((void**)&heap, g_heap);

    size_t gemm_smem  = (size_t)(2 * 64 + 128) * GPK * sizeof(__half) * 2;  // 73.7KB
    size_t flash_smem = 4 * 64 * FQP * sizeof(__half);
    cudaFuncSetAttribute((const void*)gemm_split<64,128,4>, cudaFuncAttributeMaxDynamicSharedMemorySize, (int)gemm_smem);
    cudaFuncSetAttribute((const void*)flash_attn, cudaFuncAttributeMaxDynamicSharedMemorySize, (int)flash_smem);

#define HF(off) ((__half*)(heap + off))
#define FP(off) ((float*)(heap + off))

    // 1: prep x + first-half weights
    prep_main<<<(unsigned)((N4_MAIN + 255) / 256), 256>>>(
        x, Wqkv, Aqkv, Bqkv,
        HF(O_XHI), HF(O_XLO), HF(O_WQH), HF(O_AQH), HF(O_BQH));

    // 2: T1 = LORA_SC * x @ Aqkv^T  (hi/lo output)
    gemm_split<64,128,4><<<dim3(RLORA / 128, MTOT / 64), 256, gemm_smem>>>(
        HF(O_XHI), HF(O_XLO), HF(O_XHI), HF(O_XLO),
        HF(O_AQH), HF(O_AQH),
        nullptr, HF(O_T1H), HF(O_T1L),
        RLORA, HIDDEN, 0, LORA_SC);

    // 3: prep second-half weights
    prep_sec<<<(unsigned)((N4_SEC + 255) / 256), 256>>>(
        Wo, Ao, Bo, HF(O_WOH), HF(O_AOH), HF(O_BOH));

    // 4: QKV = [x | T1] @ [Wqkv | Bqkv]^T   (fp32)   <-- ncu profiled slot
    gemm_split<64,128,4><<<dim3(OPSZ / 128, MTOT / 64), 256, gemm_smem>>>(
        HF(O_XHI), HF(O_XLO), HF(O_T1H), HF(O_T1L),
        HF(O_WQH), HF(O_BQH),
        FP(O_QKV), nullptr, nullptr,
        OPSZ, HIDDEN, RLORA, 1.0f);

    // 5: RoPE + scatter + split
    rope_split<<<MTOT, 256>>>(FP(O_QKV), pos,
        HF(O_QH), HF(O_QL), HF(O_KH), HF(O_VH));

    // 6: flash attention (writes hi/lo attn directly)
    flash_attn<<<dim3(SS / 64, NHEADS, BB), 128, flash_smem>>>(
        HF(O_QH), HF(O_QL), HF(O_KH), HF(O_VH),
        HF(O_ATH), HF(O_ATL));

    // 7: T2 = LORA_SC * attn @ Ao^T  (hi/lo output)
    gemm_split<64,128,4><<<dim3(RLORA / 128, MTOT / 64), 256, gemm_smem>>>(
        HF(O_ATH), HF(O_ATL), HF(O_ATH), HF(O_ATL),
        HF(O_AOH), HF(O_AOH),
        nullptr, HF(O_T2H), HF(O_T2L),
        RLORA, HIDDEN, 0, LORA_SC);

    // 8: out = [attn | T2] @ [Wo | Bo]^T   (fp32)
    gemm_split<64,128,4><<<dim3(HIDDEN / 128, MTOT / 64), 256, gemm_smem>>>(
        HF(O_ATH), HF(O_ATL), HF(O_T2H), HF(O_T2L),
        HF(O_WOH), HF(O_BOH),
        out, nullptr, nullptr,
        HIDDEN, HIDDEN, RLORA, 1.0f);

#undef HF
#undef FP
}